// round 14
// baseline (speedup 1.0000x reference)
#include <cuda_runtime.h>
#include <cuda_fp16.h>
#include <cstdint>
#include <cstddef>

#define BATCH 4
#define C     64
#define H     512
#define Wd    512
#define LAT   256

#define TILE_W 16
#define TILE_H 16
#define HALO   18
#define NPX    (HALO * HALO)            // 324
#define PXB    176                      // bytes per halo pixel (128B data + 48B pad)
#define XTILE_B (NPX * PXB)             // 57024
#define W_B     73728                   // 9 taps * 64oc * 128B (fp16)
#define XOFF    W_B
#define STG_OFF (W_B + 2 * XTILE_B)     // 187776
#define STG_B   (256 * 144)             // 36864
#define SMEM_SZ (STG_OFF + STG_B)       // 224640 <= 232448

// Scratch
__device__ __half g_wA0[BATCH * 36864];     // fp16 weights, ldmatrix-swizzled
__device__ __half g_wA1[BATCH * 36864];
__device__ __half g_xh [(size_t)BATCH * H * Wd * C];  // input, NHWC fp16 (ppos2-permuted)
__device__ __half g_mid[(size_t)BATCH * H * Wd * C];  // mid, same layout

__device__ __forceinline__ int refl(int v) {
    return v < 0 ? -v : (v > H - 1 ? 2 * (H - 1) - v : v);
}
// channel -> permuted position so thread t4 owns a contiguous 32B block holding
// its B-fragment halves for all 4 k16 chunks:
//   pos = t4*16 + ks*4 + j ;  t4=(c>>1)&3, ks=c>>4, j=(c&1)|((c>>2)&2)
__device__ __forceinline__ int ppos2(int c) {
    return (((c >> 1) & 3) << 4) + ((c >> 4) << 2) + ((c & 1) | ((c >> 2) & 2));
}
__device__ __forceinline__ uint32_t smem_u32(const void* p) {
    uint32_t a;
    asm("{ .reg .u64 t; cvta.to.shared.u64 t, %1; cvt.u32.u64 %0, t; }" : "=r"(a) : "l"(p));
    return a;
}
__device__ __forceinline__ void ldmA(uint32_t* r, uint32_t addr) {
    asm volatile("ldmatrix.sync.aligned.m8n8.x4.shared.b16 {%0,%1,%2,%3}, [%4];"
                 : "=r"(r[0]), "=r"(r[1]), "=r"(r[2]), "=r"(r[3]) : "r"(addr));
}
__device__ __forceinline__ void mmaF(float* c, const uint32_t* a, uint32_t b0, uint32_t b1) {
    asm volatile("mma.sync.aligned.m16n8k16.row.col.f32.f16.f16.f32 "
                 "{%0,%1,%2,%3},{%4,%5,%6,%7},{%8,%9},{%0,%1,%2,%3};"
                 : "+f"(c[0]), "+f"(c[1]), "+f"(c[2]), "+f"(c[3])
                 : "r"(a[0]), "r"(a[1]), "r"(a[2]), "r"(a[3]), "r"(b0), "r"(b1));
}
__device__ __forceinline__ void cpa16(uint32_t ds, const void* gp) {
    asm volatile("cp.async.cg.shared.global [%0], [%1], 16;" :: "r"(ds), "l"(gp) : "memory");
}

// ---------------------------------------------------------------------------
// Input convert: NCHW fp32 -> NHWC fp16 ppos2-permuted.
// smem stride 78 halfs = 39 words (odd) -> conflict-free stores AND loads.
// grid (4, 512, 4): block = (x-quarter, y, b); each block does 4 x-chunks of 32.
// ---------------------------------------------------------------------------
__global__ void __launch_bounds__(256) xcvt(const float* __restrict__ x) {
    __shared__ __align__(16) __half st[32 * 78];
    const int y = blockIdx.y, b = blockIdx.z;
    const int t = threadIdx.x;
    for (int j = 0; j < 4; ++j) {
        const int x0 = blockIdx.x * 128 + j * 32;
        #pragma unroll
        for (int it = 0; it < 4; ++it) {
            int i  = it * 256 + t;          // 0..1023
            int cp = i >> 5;                // channel pair 0..31
            int xx = i & 31;
            const float* p = &x[(((size_t)b * 64 + 2 * cp) * 512 + y) * 512 + x0 + xx];
            float f0 = p[0];
            float f1 = p[262144];           // next channel plane
            __half2 h = __floats2half2_rn(f0, f1);
            *(__half2*)&st[xx * 78 + ppos2(2 * cp)] = h;   // ppos2(2cp+1)=+1
        }
        __syncthreads();
        {
            int px = t >> 3, ch = t & 7;
            const uint32_t* sp = (const uint32_t*)&st[px * 78 + ch * 8];
            uint4 v = make_uint4(sp[0], sp[1], sp[2], sp[3]);
            *(uint4*)&g_xh[(((size_t)b * 512 + y) * 512 + x0 + px) * 64 + ch * 8] = v;
        }
        __syncthreads();
    }
}

// ---------------------------------------------------------------------------
// Prep (both passes): fold modulation + demod; emit fp16 weights swizzled for
// ldmatrix. blockIdx = (batch, pass). elem(oc,ic) at
// oc*64 + (((ic>>3)^(oc&7))*8) + (ic&7).
// ---------------------------------------------------------------------------
__global__ void prep_kernel(const float* __restrict__ latent,
                            const float* __restrict__ w0g,
                            const float* __restrict__ mw0g,
                            const float* __restrict__ mb0g,
                            const float* __restrict__ w1g,
                            const float* __restrict__ mw1g,
                            const float* __restrict__ mb1g) {
    const int pass = blockIdx.y;
    const float* w  = pass ? w1g  : w0g;
    const float* mw = pass ? mw1g : mw0g;
    const float* mb = pass ? mb1g : mb0g;
    __half* gw = pass ? g_wA1 : g_wA0;
    __shared__ float s[C];
    __shared__ float d[C];
    const int b = blockIdx.x;
    const int t = threadIdx.x;
    const float lscale = 0.08838834764831845f;   // sqrt(2/256)
    const float wscale = 0.05892556509887896f;   // sqrt(2/576)

    if (t < C) {
        float acc = 0.f;
        const float* lb  = latent + b * LAT;
        const float* mwr = mw + t * LAT;
        #pragma unroll 4
        for (int l = 0; l < LAT; ++l) acc += lb[l] * mwr[l];
        s[t] = 1.f + acc * lscale + mb[t];
    }
    __syncthreads();
    if (t < C) {
        float acc = 0.f;
        for (int i = 0; i < C; ++i) {
            float wsq = 0.f;
            const float* wr = w + (t * C + i) * 9;
            #pragma unroll
            for (int k = 0; k < 9; ++k) { float v = wr[k]; wsq += v * v; }
            acc += s[i] * s[i] * wsq;
        }
        d[t] = rsqrtf(acc * wscale * wscale + 1e-5f);
    }
    __syncthreads();
    for (int idx = t; idx < 9 * 64 * 64; idx += blockDim.x) {
        int ic  = idx & 63;
        int o   = (idx >> 6) & 63;
        int tap = idx >> 12;
        float v = d[o] * s[ic] * w[(o * 64 + ic) * 9 + tap] * wscale;
        int e = o * 64 + (((ic >> 3) ^ (o & 7)) << 3) + (ic & 7);
        gw[b * 36864 + tap * 4096 + e] = __float2half_rn(v);
    }
}

// ---------------------------------------------------------------------------
// Persistent mma.sync conv. 148 CTAs = 4 batch x 37. fp16 weights in smem.
// Tile = 16x16 px, all 64 oc. Warp tile M32 x N64 (ocg = wid&1, pxg = wid>>1).
// Per tap: 8 ldmatrix.x4 (A, all 4 k-chunks) + 16 LDS.128 (B) + 64 HMMA.
// Halo double-buffered via cp.async.
// ---------------------------------------------------------------------------
template <int PASS>
__global__ void __launch_bounds__(256, 1)
conv_mma(const float* __restrict__ bias_g, float* __restrict__ xout) {
    extern __shared__ __align__(16) char smem[];
    const __half* src  = (PASS == 0) ? g_xh : g_mid;
    const __half* wsrc = (PASS == 0) ? g_wA0 : g_wA1;

    const int tid = threadIdx.x, wrp = tid >> 5, lane = tid & 31;
    const int cta = blockIdx.x;
    const int b = cta / 37, i37 = cta % 37;
    const int t0 = (1024 * i37) / 37, t1 = (1024 * (i37 + 1)) / 37;
    const uint32_t sb = smem_u32(smem);

    const int ocg = wrp & 1;       // oc group (32)
    const int pxg = wrp >> 1;      // 0..3 -> 64 pixels each

    // Weights: one 73728B copy per CTA lifetime
    {
        const uint4* wsv = (const uint4*)(wsrc + (size_t)b * 36864);
        uint4* wdv = (uint4*)smem;
        for (int i = tid; i < W_B / 16; i += 256) wdv[i] = wsv[i];
    }

    const __half* srcb = src + (size_t)b * (512 * 512 * 64);
    __half*       dsth = g_mid + (size_t)b * (512 * 512 * 64);
    const size_t plane = (size_t)H * Wd;
    float* dstf = xout + (size_t)b * C * plane;

    const int g  = lane >> 2;
    const int t4 = lane & 3;
    const int arow = lane & 15, aku = lane >> 4, asw = arow & 7;
    const uint32_t abase = sb + (uint32_t)(ocg * 4096 + arow * 128);

    // loop-invariant B pixel bases
    int pixB[8];
    #pragma unroll
    for (int nt = 0; nt < 8; ++nt) {
        int p = pxg * 64 + nt * 8 + g;
        pixB[nt] = ((p >> 4) * HALO + (p & 15)) * PXB + t4 * 32;
    }

    float biasv[2][2];
    #pragma unroll
    for (int mf = 0; mf < 2; ++mf)
        #pragma unroll
        for (int h = 0; h < 2; ++h)
            biasv[mf][h] = bias_g[ocg * 32 + mf * 16 + g + h * 8];

    const float gain = 1.4142135623730951f;

    auto halo = [&](int tix, int bufsel) {
        const int y0 = (tix >> 5) * TILE_H, x0 = (tix & 31) * TILE_W;
        for (int item = tid; item < NPX * 8; item += 256) {
            int px = item >> 3, ch = item & 7;
            int r = px / HALO, cc = px - r * HALO;
            int gy = refl(y0 - 1 + r);
            int gx = refl(x0 - 1 + cc);
            const __half* gp = srcb + ((size_t)gy * 512 + gx) * 64 + ch * 8;
            uint32_t ds = sb + XOFF + (uint32_t)(bufsel * XTILE_B + px * PXB + ch * 16);
            cpa16(ds, gp);
        }
        asm volatile("cp.async.commit_group;" ::: "memory");
    };

    halo(t0, t0 & 1);

    for (int tix = t0; tix < t1; ++tix) {
        __syncthreads();   // prior tile fully consumed
        if (tix + 1 < t1) {
            halo(tix + 1, (tix + 1) & 1);
            asm volatile("cp.async.wait_group 1;" ::: "memory");
        } else {
            asm volatile("cp.async.wait_group 0;" ::: "memory");
        }
        __syncthreads();   // halo(tix) visible

        const int y0 = (tix >> 5) * TILE_H, x0 = (tix & 31) * TILE_W;
        const char* xb = smem + XOFF + (size_t)(tix & 1) * XTILE_B;

        float acc[2][8][4];
        #pragma unroll
        for (int mf = 0; mf < 2; ++mf)
            #pragma unroll
            for (int nt = 0; nt < 8; ++nt)
                #pragma unroll
                for (int q = 0; q < 4; ++q) acc[mf][nt][q] = 0.f;

        #pragma unroll 1
        for (int tap = 0; tap < 9; ++tap) {
            const int ky = tap / 3;
            const int kx = tap - 3 * ky;
            const int tapOff = (ky * HALO + kx) * PXB;

            uint32_t A0[4][4], A1[4][4];
            const uint32_t ah = abase + (uint32_t)(tap * 8192);
            #pragma unroll
            for (int ks = 0; ks < 4; ++ks) {
                uint32_t a = ah + (uint32_t)((((ks << 1) | aku) ^ asw) << 4);
                ldmA(A0[ks], a);
                ldmA(A1[ks], a + 2048);
            }
            #pragma unroll
            for (int nt = 0; nt < 8; ++nt) {
                const char* ba = xb + pixB[nt] + tapOff;
                uint4 q0 = *(const uint4*)(ba);
                uint4 q1 = *(const uint4*)(ba + 16);
                mmaF(acc[0][nt], A0[0], q0.x, q0.y);
                mmaF(acc[1][nt], A1[0], q0.x, q0.y);
                mmaF(acc[0][nt], A0[1], q0.z, q0.w);
                mmaF(acc[1][nt], A1[1], q0.z, q0.w);
                mmaF(acc[0][nt], A0[2], q1.x, q1.y);
                mmaF(acc[1][nt], A1[2], q1.x, q1.y);
                mmaF(acc[0][nt], A0[3], q1.z, q1.w);
                mmaF(acc[1][nt], A1[3], q1.z, q1.w);
            }
        }

        // ---- epilogue ----
        #pragma unroll
        for (int mf = 0; mf < 2; ++mf)
            #pragma unroll
            for (int nt = 0; nt < 8; ++nt) {
                float v0 = acc[mf][nt][0] + biasv[mf][0];
                float v1 = acc[mf][nt][1] + biasv[mf][0];
                float v2 = acc[mf][nt][2] + biasv[mf][1];
                float v3 = acc[mf][nt][3] + biasv[mf][1];
                v0 = (v0 >= 0.f ? v0 : 0.2f * v0) * gain;
                v1 = (v1 >= 0.f ? v1 : 0.2f * v1) * gain;
                v2 = (v2 >= 0.f ? v2 : 0.2f * v2) * gain;
                v3 = (v3 >= 0.f ? v3 : 0.2f * v3) * gain;
                int px0 = pxg * 64 + nt * 8 + 2 * t4;
                if (PASS == 0) {
                    __half* stp = (__half*)(smem + STG_OFF);
                    int oc0 = ocg * 32 + mf * 16 + g;
                    int p0 = ppos2(oc0);          // h=1 channel sits at p0+2
                    stp[px0 * 72 + p0]           = __float2half_rn(v0);
                    stp[(px0 + 1) * 72 + p0]     = __float2half_rn(v1);
                    stp[px0 * 72 + p0 + 2]       = __float2half_rn(v2);
                    stp[(px0 + 1) * 72 + p0 + 2] = __float2half_rn(v3);
                } else {
                    int oc = ocg * 32 + mf * 16 + g;
                    int pr = px0 >> 4, pc = px0 & 15;
                    float* dp = dstf + (size_t)oc * plane + (size_t)(y0 + pr) * Wd + x0 + pc;
                    *(float2*)dp = make_float2(v0, v1);
                    *(float2*)(dp + 8 * plane) = make_float2(v2, v3);
                }
            }

        if (PASS == 0) {
            __syncthreads();
            int px = tid;
            const uint4* sp = (const uint4*)(smem + STG_OFF + px * 144);
            int gy = y0 + (px >> 4), gx = x0 + (px & 15);
            uint4* gp = (uint4*)(dsth + ((size_t)gy * 512 + gx) * 64);
            #pragma unroll
            for (int j = 0; j < 8; ++j) gp[j] = sp[j];
        }
    }
}

extern "C" void kernel_launch(void* const* d_in, const int* in_sizes, int n_in,
                              void* d_out, int out_size) {
    const float* x      = (const float*)d_in[0];
    const float* latent = (const float*)d_in[1];
    const float* w0     = (const float*)d_in[2];
    const float* b0     = (const float*)d_in[3];
    const float* mw0    = (const float*)d_in[4];
    const float* mb0    = (const float*)d_in[5];
    const float* w1     = (const float*)d_in[6];
    const float* b1     = (const float*)d_in[7];
    const float* mw1    = (const float*)d_in[8];
    const float* mb1    = (const float*)d_in[9];
    float* out = (float*)d_out;

    cudaFuncSetAttribute(conv_mma<0>, cudaFuncAttributeMaxDynamicSharedMemorySize, SMEM_SZ);
    cudaFuncSetAttribute(conv_mma<1>, cudaFuncAttributeMaxDynamicSharedMemorySize, SMEM_SZ);

    xcvt<<<dim3(4, 512, 4), 256>>>(x);
    prep_kernel<<<dim3(BATCH, 2), 256>>>(latent, w0, mw0, mb0, w1, mw1, mb1);

    conv_mma<0><<<148, 256, SMEM_SZ>>>(b0, nullptr);
    conv_mma<1><<<148, 256, SMEM_SZ>>>(b1, out);
}

// round 15
// speedup vs baseline: 1.5097x; 1.5097x over previous
#include <cuda_runtime.h>
#include <cuda_fp16.h>
#include <cstdint>
#include <cstddef>

#define BATCH 4
#define C     64
#define H     512
#define Wd    512
#define LAT   256

#define TILE_W 16
#define TILE_H 16
#define HALO   18
#define NPX    (HALO * HALO)            // 324
#define PXB    176                      // bytes per halo pixel (128B data + 48B pad)
#define XTILE_B (NPX * PXB)             // 57024
#define W_B     73728                   // 9 taps * 64oc * 128B (fp16)
#define XOFF    W_B
#define STG_OFF (W_B + 2 * XTILE_B)     // 187776
#define STG_B   (256 * 144)             // 36864
#define SMEM_SZ (STG_OFF + STG_B)       // 224640 <= 232448

#define NTHR 512

// Scratch
__device__ __half g_wA0[BATCH * 36864];     // fp16 weights, ldmatrix-swizzled
__device__ __half g_wA1[BATCH * 36864];
__device__ __half g_xh [(size_t)BATCH * H * Wd * C];  // input, NHWC fp16 (ppos2-permuted)
__device__ __half g_mid[(size_t)BATCH * H * Wd * C];  // mid, same layout

__device__ __forceinline__ int refl(int v) {
    return v < 0 ? -v : (v > H - 1 ? 2 * (H - 1) - v : v);
}
// channel -> permuted position so thread t4 owns a contiguous 32B block holding
// its B-fragment halves for all 4 k16 chunks:
//   pos = t4*16 + ks*4 + j ;  t4=(c>>1)&3, ks=c>>4, j=(c&1)|((c>>2)&2)
__device__ __forceinline__ int ppos2(int c) {
    return (((c >> 1) & 3) << 4) + ((c >> 4) << 2) + ((c & 1) | ((c >> 2) & 2));
}
__device__ __forceinline__ uint32_t smem_u32(const void* p) {
    uint32_t a;
    asm("{ .reg .u64 t; cvta.to.shared.u64 t, %1; cvt.u32.u64 %0, t; }" : "=r"(a) : "l"(p));
    return a;
}
__device__ __forceinline__ void ldmA(uint32_t* r, uint32_t addr) {
    asm volatile("ldmatrix.sync.aligned.m8n8.x4.shared.b16 {%0,%1,%2,%3}, [%4];"
                 : "=r"(r[0]), "=r"(r[1]), "=r"(r[2]), "=r"(r[3]) : "r"(addr));
}
__device__ __forceinline__ void mmaF(float* c, const uint32_t* a, uint32_t b0, uint32_t b1) {
    asm volatile("mma.sync.aligned.m16n8k16.row.col.f32.f16.f16.f32 "
                 "{%0,%1,%2,%3},{%4,%5,%6,%7},{%8,%9},{%0,%1,%2,%3};"
                 : "+f"(c[0]), "+f"(c[1]), "+f"(c[2]), "+f"(c[3])
                 : "r"(a[0]), "r"(a[1]), "r"(a[2]), "r"(a[3]), "r"(b0), "r"(b1));
}
__device__ __forceinline__ void cpa16(uint32_t ds, const void* gp) {
    asm volatile("cp.async.cg.shared.global [%0], [%1], 16;" :: "r"(ds), "l"(gp) : "memory");
}

// ---------------------------------------------------------------------------
// Input convert: NCHW fp32 -> NHWC fp16 ppos2-permuted.
// smem stride 78 halfs = 39 words (odd) -> conflict-free stores AND loads.
// ---------------------------------------------------------------------------
__global__ void __launch_bounds__(256) xcvt(const float* __restrict__ x) {
    __shared__ __align__(16) __half st[32 * 78];
    const int y = blockIdx.y, b = blockIdx.z;
    const int t = threadIdx.x;
    for (int j = 0; j < 4; ++j) {
        const int x0 = blockIdx.x * 128 + j * 32;
        #pragma unroll
        for (int it = 0; it < 4; ++it) {
            int i  = it * 256 + t;          // 0..1023
            int cp = i >> 5;                // channel pair 0..31
            int xx = i & 31;
            const float* p = &x[(((size_t)b * 64 + 2 * cp) * 512 + y) * 512 + x0 + xx];
            float f0 = p[0];
            float f1 = p[262144];           // next channel plane
            __half2 h = __floats2half2_rn(f0, f1);
            *(__half2*)&st[xx * 78 + ppos2(2 * cp)] = h;   // ppos2(2cp+1)=+1
        }
        __syncthreads();
        {
            int px = t >> 3, ch = t & 7;
            const uint32_t* sp = (const uint32_t*)&st[px * 78 + ch * 8];
            uint4 v = make_uint4(sp[0], sp[1], sp[2], sp[3]);
            *(uint4*)&g_xh[(((size_t)b * 512 + y) * 512 + x0 + px) * 64 + ch * 8] = v;
        }
        __syncthreads();
    }
}

// ---------------------------------------------------------------------------
// Prep (both passes): fold modulation + demod; emit fp16 weights swizzled for
// ldmatrix. blockIdx = (batch, pass). elem(oc,ic) at
// oc*64 + (((ic>>3)^(oc&7))*8) + (ic&7).
// ---------------------------------------------------------------------------
__global__ void prep_kernel(const float* __restrict__ latent,
                            const float* __restrict__ w0g,
                            const float* __restrict__ mw0g,
                            const float* __restrict__ mb0g,
                            const float* __restrict__ w1g,
                            const float* __restrict__ mw1g,
                            const float* __restrict__ mb1g) {
    const int pass = blockIdx.y;
    const float* w  = pass ? w1g  : w0g;
    const float* mw = pass ? mw1g : mw0g;
    const float* mb = pass ? mb1g : mb0g;
    __half* gw = pass ? g_wA1 : g_wA0;
    __shared__ float s[C];
    __shared__ float d[C];
    const int b = blockIdx.x;
    const int t = threadIdx.x;
    const float lscale = 0.08838834764831845f;   // sqrt(2/256)
    const float wscale = 0.05892556509887896f;   // sqrt(2/576)

    if (t < C) {
        float acc = 0.f;
        const float* lb  = latent + b * LAT;
        const float* mwr = mw + t * LAT;
        #pragma unroll 4
        for (int l = 0; l < LAT; ++l) acc += lb[l] * mwr[l];
        s[t] = 1.f + acc * lscale + mb[t];
    }
    __syncthreads();
    if (t < C) {
        float acc = 0.f;
        for (int i = 0; i < C; ++i) {
            float wsq = 0.f;
            const float* wr = w + (t * C + i) * 9;
            #pragma unroll
            for (int k = 0; k < 9; ++k) { float v = wr[k]; wsq += v * v; }
            acc += s[i] * s[i] * wsq;
        }
        d[t] = rsqrtf(acc * wscale * wscale + 1e-5f);
    }
    __syncthreads();
    for (int idx = t; idx < 9 * 64 * 64; idx += blockDim.x) {
        int ic  = idx & 63;
        int o   = (idx >> 6) & 63;
        int tap = idx >> 12;
        float v = d[o] * s[ic] * w[(o * 64 + ic) * 9 + tap] * wscale;
        int e = o * 64 + (((ic >> 3) ^ (o & 7)) << 3) + (ic & 7);
        gw[b * 36864 + tap * 4096 + e] = __float2half_rn(v);
    }
}

// ---------------------------------------------------------------------------
// Persistent mma.sync conv. 148 CTAs = 4 batch x 37. fp16 weights in smem.
// 512 threads = 16 warps (4/SMSP for latency hiding).
// Tile = 16x16 px, all 64 oc. Warp tile M32 x N32 (ocg = wid&1, pxg = wid>>1).
// Per tap per warp: 8 ldmatrix.x4 + 8 LDS.128 + 32 HMMA.
// Halo double-buffered via cp.async.
// ---------------------------------------------------------------------------
template <int PASS>
__global__ void __launch_bounds__(NTHR, 1)
conv_mma(const float* __restrict__ bias_g, float* __restrict__ xout) {
    extern __shared__ __align__(16) char smem[];
    const __half* src  = (PASS == 0) ? g_xh : g_mid;
    const __half* wsrc = (PASS == 0) ? g_wA0 : g_wA1;

    const int tid = threadIdx.x, wrp = tid >> 5, lane = tid & 31;
    const int cta = blockIdx.x;
    const int b = cta / 37, i37 = cta % 37;
    const int t0 = (1024 * i37) / 37, t1 = (1024 * (i37 + 1)) / 37;
    const uint32_t sb = smem_u32(smem);

    const int ocg = wrp & 1;       // oc group (32)
    const int pxg = wrp >> 1;      // 0..7 -> 32 pixels each

    // Weights: one 73728B copy per CTA lifetime
    {
        const uint4* wsv = (const uint4*)(wsrc + (size_t)b * 36864);
        uint4* wdv = (uint4*)smem;
        for (int i = tid; i < W_B / 16; i += NTHR) wdv[i] = wsv[i];
    }

    const __half* srcb = src + (size_t)b * (512 * 512 * 64);
    __half*       dsth = g_mid + (size_t)b * (512 * 512 * 64);
    const size_t plane = (size_t)H * Wd;
    float* dstf = xout + (size_t)b * C * plane;

    const int g  = lane >> 2;
    const int t4 = lane & 3;
    const int arow = lane & 15, aku = lane >> 4, asw = arow & 7;
    const uint32_t abase = sb + (uint32_t)(ocg * 4096 + arow * 128);

    // loop-invariant B pixel bases (4 n8-groups per warp)
    int pixB[4];
    #pragma unroll
    for (int nt = 0; nt < 4; ++nt) {
        int p = pxg * 32 + nt * 8 + g;
        pixB[nt] = ((p >> 4) * HALO + (p & 15)) * PXB + t4 * 32;
    }

    float biasv[2][2];
    #pragma unroll
    for (int mf = 0; mf < 2; ++mf)
        #pragma unroll
        for (int h = 0; h < 2; ++h)
            biasv[mf][h] = bias_g[ocg * 32 + mf * 16 + g + h * 8];

    const float gain = 1.4142135623730951f;

    auto halo = [&](int tix, int bufsel) {
        const int y0 = (tix >> 5) * TILE_H, x0 = (tix & 31) * TILE_W;
        for (int item = tid; item < NPX * 8; item += NTHR) {
            int px = item >> 3, ch = item & 7;
            int r = px / HALO, cc = px - r * HALO;
            int gy = refl(y0 - 1 + r);
            int gx = refl(x0 - 1 + cc);
            const __half* gp = srcb + ((size_t)gy * 512 + gx) * 64 + ch * 8;
            uint32_t ds = sb + XOFF + (uint32_t)(bufsel * XTILE_B + px * PXB + ch * 16);
            cpa16(ds, gp);
        }
        asm volatile("cp.async.commit_group;" ::: "memory");
    };

    halo(t0, t0 & 1);

    for (int tix = t0; tix < t1; ++tix) {
        __syncthreads();   // prior tile fully consumed
        if (tix + 1 < t1) {
            halo(tix + 1, (tix + 1) & 1);
            asm volatile("cp.async.wait_group 1;" ::: "memory");
        } else {
            asm volatile("cp.async.wait_group 0;" ::: "memory");
        }
        __syncthreads();   // halo(tix) visible

        const int y0 = (tix >> 5) * TILE_H, x0 = (tix & 31) * TILE_W;
        const char* xb = smem + XOFF + (size_t)(tix & 1) * XTILE_B;

        float acc[2][4][4];
        #pragma unroll
        for (int mf = 0; mf < 2; ++mf)
            #pragma unroll
            for (int nt = 0; nt < 4; ++nt)
                #pragma unroll
                for (int q = 0; q < 4; ++q) acc[mf][nt][q] = 0.f;

        #pragma unroll 1
        for (int tap = 0; tap < 9; ++tap) {
            const int ky = tap / 3;
            const int kx = tap - 3 * ky;
            const int tapOff = (ky * HALO + kx) * PXB;

            uint32_t A0[4][4], A1[4][4];
            const uint32_t ah = abase + (uint32_t)(tap * 8192);
            #pragma unroll
            for (int ks = 0; ks < 4; ++ks) {
                uint32_t a = ah + (uint32_t)((((ks << 1) | aku) ^ asw) << 4);
                ldmA(A0[ks], a);
                ldmA(A1[ks], a + 2048);
            }
            #pragma unroll
            for (int nt = 0; nt < 4; ++nt) {
                const char* ba = xb + pixB[nt] + tapOff;
                uint4 q0 = *(const uint4*)(ba);
                uint4 q1 = *(const uint4*)(ba + 16);
                mmaF(acc[0][nt], A0[0], q0.x, q0.y);
                mmaF(acc[1][nt], A1[0], q0.x, q0.y);
                mmaF(acc[0][nt], A0[1], q0.z, q0.w);
                mmaF(acc[1][nt], A1[1], q0.z, q0.w);
                mmaF(acc[0][nt], A0[2], q1.x, q1.y);
                mmaF(acc[1][nt], A1[2], q1.x, q1.y);
                mmaF(acc[0][nt], A0[3], q1.z, q1.w);
                mmaF(acc[1][nt], A1[3], q1.z, q1.w);
            }
        }

        // ---- epilogue ----
        #pragma unroll
        for (int mf = 0; mf < 2; ++mf)
            #pragma unroll
            for (int nt = 0; nt < 4; ++nt) {
                float v0 = acc[mf][nt][0] + biasv[mf][0];
                float v1 = acc[mf][nt][1] + biasv[mf][0];
                float v2 = acc[mf][nt][2] + biasv[mf][1];
                float v3 = acc[mf][nt][3] + biasv[mf][1];
                v0 = (v0 >= 0.f ? v0 : 0.2f * v0) * gain;
                v1 = (v1 >= 0.f ? v1 : 0.2f * v1) * gain;
                v2 = (v2 >= 0.f ? v2 : 0.2f * v2) * gain;
                v3 = (v3 >= 0.f ? v3 : 0.2f * v3) * gain;
                int px0 = pxg * 32 + nt * 8 + 2 * t4;
                if (PASS == 0) {
                    __half* stp = (__half*)(smem + STG_OFF);
                    int oc0 = ocg * 32 + mf * 16 + g;
                    int p0 = ppos2(oc0);          // h=1 channel sits at p0+2
                    stp[px0 * 72 + p0]           = __float2half_rn(v0);
                    stp[(px0 + 1) * 72 + p0]     = __float2half_rn(v1);
                    stp[px0 * 72 + p0 + 2]       = __float2half_rn(v2);
                    stp[(px0 + 1) * 72 + p0 + 2] = __float2half_rn(v3);
                } else {
                    int oc = ocg * 32 + mf * 16 + g;
                    int pr = px0 >> 4, pc = px0 & 15;
                    float* dp = dstf + (size_t)oc * plane + (size_t)(y0 + pr) * Wd + x0 + pc;
                    *(float2*)dp = make_float2(v0, v1);
                    *(float2*)(dp + 8 * plane) = make_float2(v2, v3);
                }
            }

        if (PASS == 0) {
            __syncthreads();
            int px = tid >> 1, hf = tid & 1;   // 512 threads: half-pixel each
            const uint4* sp = (const uint4*)(smem + STG_OFF + px * 144 + hf * 64);
            int gy = y0 + (px >> 4), gx = x0 + (px & 15);
            uint4* gp = (uint4*)(dsth + ((size_t)gy * 512 + gx) * 64 + hf * 32);
            #pragma unroll
            for (int j = 0; j < 4; ++j) gp[j] = sp[j];
        }
    }
}

extern "C" void kernel_launch(void* const* d_in, const int* in_sizes, int n_in,
                              void* d_out, int out_size) {
    const float* x      = (const float*)d_in[0];
    const float* latent = (const float*)d_in[1];
    const float* w0     = (const float*)d_in[2];
    const float* b0     = (const float*)d_in[3];
    const float* mw0    = (const float*)d_in[4];
    const float* mb0    = (const float*)d_in[5];
    const float* w1     = (const float*)d_in[6];
    const float* b1     = (const float*)d_in[7];
    const float* mw1    = (const float*)d_in[8];
    const float* mb1    = (const float*)d_in[9];
    float* out = (float*)d_out;

    cudaFuncSetAttribute(conv_mma<0>, cudaFuncAttributeMaxDynamicSharedMemorySize, SMEM_SZ);
    cudaFuncSetAttribute(conv_mma<1>, cudaFuncAttributeMaxDynamicSharedMemorySize, SMEM_SZ);

    xcvt<<<dim3(4, 512, 4), 256>>>(x);
    prep_kernel<<<dim3(BATCH, 2), 256>>>(latent, w0, mw0, mb0, w1, mw1, mb1);

    conv_mma<0><<<148, NTHR, SMEM_SZ>>>(b0, nullptr);
    conv_mma<1><<<148, NTHR, SMEM_SZ>>>(b1, out);
}